// round 4
// baseline (speedup 1.0000x reference)
#include <cuda_runtime.h>
#include <cuda_bf16.h>

// Problem constants (fixed for this dataset)
#define NMAX 50000
#define RREL 8
#define FIN  128
#define KTOT ((RREL + 1) * FIN)   // 1152

// Scratch (device globals — allocation-free per harness rules)
__device__ float g_agg[NMAX * RREL * FIN];   // 204.8 MB: per-(node,rel) mean-aggregated features
__device__ float g_h0[NMAX * FIN];           // layer 0 output
__device__ float g_h1[NMAX * FIN];           // layer 1 output
__device__ int   g_cnt[NMAX * RREL];
__device__ float g_inv[NMAX * RREL];

// ---------------------------------------------------------------------------
__global__ void zero_cnt_k(int nr) {
    int i = blockIdx.x * blockDim.x + threadIdx.x;
    if (i < nr) g_cnt[i] = 0;
}

__global__ void count_k(const int* __restrict__ dst, const int* __restrict__ et, int e) {
    int i = blockIdx.x * blockDim.x + threadIdx.x;
    if (i < e) atomicAdd(&g_cnt[dst[i] * RREL + et[i]], 1);
}

__global__ void inv_k(int nr) {
    int i = blockIdx.x * blockDim.x + threadIdx.x;
    if (i < nr) {
        int c = g_cnt[i];
        g_inv[i] = 1.0f / (float)(c > 1 ? c : 1);
    }
}

__global__ void zero_agg_k(int n4) {
    int i = blockIdx.x * blockDim.x + threadIdx.x;
    if (i < n4) reinterpret_cast<float4*>(g_agg)[i] = make_float4(0.f, 0.f, 0.f, 0.f);
}

// One warp per edge: lane L handles features [4L, 4L+4). X fits in L2, so the
// gather is cheap; the atomics are the scattered part.
__global__ void scatter_k(const float* __restrict__ X,
                          const int* __restrict__ src, const int* __restrict__ dst,
                          const int* __restrict__ et, int e) {
    int gw   = (blockIdx.x * blockDim.x + threadIdx.x) >> 5;
    int lane = threadIdx.x & 31;
    if (gw >= e) return;
    int s = src[gw], d = dst[gw], t = et[gw];
    float w = g_inv[d * RREL + t];
    float4 v = reinterpret_cast<const float4*>(X + (size_t)s * FIN)[lane];
    float* base = g_agg + (size_t)d * (RREL * FIN) + t * FIN + lane * 4;
    atomicAdd(base + 0, v.x * w);
    atomicAdd(base + 1, v.y * w);
    atomicAdd(base + 2, v.z * w);
    atomicAdd(base + 3, v.w * w);
}

// ---------------------------------------------------------------------------
// Fused GEMM: C = [X | AGG](N x 1152) @ [root ; Wflat](1152 x FOUT) + bias, opt ReLU.
// A k-tiles never straddle the X/AGG boundary (BK | 128).
template<int FOUT, bool RELU>
__global__ void gemm_k(const float* __restrict__ X,
                       const float* __restrict__ root,
                       const float* __restrict__ W,     // [R*FIN, FOUT] flat
                       const float* __restrict__ bias,
                       float* __restrict__ out, int n) {
    constexpr int BM = 64, BK = 16, BN = FOUT;
    constexpr int TM = 4, TN = FOUT / 16;

    __shared__ float As[BK][BM];
    __shared__ float Bs[BK][BN];

    const int tid = threadIdx.x;          // 256 threads
    const int tx  = tid % 16;
    const int ty  = tid / 16;
    const int m0  = blockIdx.x * BM;

    float acc[TM][TN];
#pragma unroll
    for (int a = 0; a < TM; a++)
#pragma unroll
        for (int b = 0; b < TN; b++) acc[a][b] = 0.f;

    for (int k0 = 0; k0 < KTOT; k0 += BK) {
        const float* Aptr;
        int astride;
        const float* Bptr;
        if (k0 < FIN) {
            Aptr = X + k0;           astride = FIN;
            Bptr = root + k0 * FOUT;
        } else {
            Aptr = g_agg + (k0 - FIN); astride = RREL * FIN;
            Bptr = W + (size_t)(k0 - FIN) * FOUT;
        }

        // Load A tile (BM*BK = 1024 elems, 4 per thread)
#pragma unroll
        for (int i = tid; i < BM * BK; i += 256) {
            int m = i / BK, k = i % BK;
            int gm = m0 + m;
            As[k][m] = (gm < n) ? Aptr[(size_t)gm * astride + k] : 0.f;
        }
        // Load B tile (BK*BN elems)
#pragma unroll
        for (int i = tid; i < BK * BN; i += 256) {
            int k = i / BN, nn = i % BN;
            Bs[k][nn] = Bptr[k * FOUT + nn];
        }
        __syncthreads();

#pragma unroll
        for (int k = 0; k < BK; k++) {
            float ra[TM], rb[TN];
#pragma unroll
            for (int a = 0; a < TM; a++) ra[a] = As[k][ty * TM + a];
#pragma unroll
            for (int b = 0; b < TN; b++) rb[b] = Bs[k][tx * TN + b];
#pragma unroll
            for (int a = 0; a < TM; a++)
#pragma unroll
                for (int b = 0; b < TN; b++) acc[a][b] += ra[a] * rb[b];
        }
        __syncthreads();
    }

#pragma unroll
    for (int a = 0; a < TM; a++) {
        int gm = m0 + ty * TM + a;
        if (gm >= n) continue;
#pragma unroll
        for (int b = 0; b < TN; b++) {
            int nn = tx * TN + b;
            float v = acc[a][b] + bias[nn];
            if (RELU) v = fmaxf(v, 0.f);
            out[(size_t)gm * FOUT + nn] = v;
        }
    }
}

// ---------------------------------------------------------------------------
template<int FOUT, bool RELU>
static void run_layer(const float* X, const int* src, const int* dst, const int* et,
                      const float* root, const float* W, const float* bias,
                      float* out, int n, int e) {
    int nr = n * RREL;
    zero_cnt_k<<<(nr + 255) / 256, 256>>>(nr);
    count_k<<<(e + 255) / 256, 256>>>(dst, et, e);
    inv_k<<<(nr + 255) / 256, 256>>>(nr);
    int n4 = (n * RREL * FIN) / 4;
    zero_agg_k<<<(n4 + 255) / 256, 256>>>(n4);
    scatter_k<<<(e * 32 + 255) / 256, 256>>>(X, src, dst, et, e);
    gemm_k<FOUT, RELU><<<(n + 63) / 64, 256>>>(X, root, W, bias, out, n);
}

extern "C" void kernel_launch(void* const* d_in, const int* in_sizes, int n_in,
                              void* d_out, int out_size) {
    const float* x    = (const float*)d_in[0];
    const int*   eidx = (const int*)d_in[1];
    const int*   et   = (const int*)d_in[2];
    const float* w0   = (const float*)d_in[3];
    const float* r0   = (const float*)d_in[4];
    const float* b0   = (const float*)d_in[5];
    const float* w1   = (const float*)d_in[6];
    const float* r1   = (const float*)d_in[7];
    const float* b1   = (const float*)d_in[8];
    const float* w2   = (const float*)d_in[9];
    const float* r2   = (const float*)d_in[10];
    const float* b2   = (const float*)d_in[11];
    float* out = (float*)d_out;

    int n = in_sizes[0] / FIN;   // 50000
    int e = in_sizes[2];         // 800000
    const int* src = eidx;       // edge_index[0]
    const int* dst = eidx + e;   // edge_index[1]

    float* h0;
    float* h1;
    cudaGetSymbolAddress((void**)&h0, g_h0);
    cudaGetSymbolAddress((void**)&h1, g_h1);

    // Layer 0: 128 -> 128, ReLU
    run_layer<128, true>(x, src, dst, et, r0, w0, b0, h0, n, e);
    // Layer 1: 128 -> 128, ReLU
    run_layer<128, true>(h0, src, dst, et, r1, w1, b1, h1, n, e);
    // Layer 2: 128 -> 16, no activation
    run_layer<16, false>(h1, src, dst, et, r2, w2, b2, out, n, e);
}

// round 7
// speedup vs baseline: 4.1841x; 4.1841x over previous
#include <cuda_runtime.h>
#include <cuda_bf16.h>
#include <cstdint>

// Problem constants (fixed dataset)
#define NMAX 50000
#define RREL 8
#define FIN  128
#define NB   (NMAX * RREL)          // 400000 segment bins
#define CS   ((size_t)NMAX * 128)   // Y chunk stride (floats)

// ---------------- device scratch (allocation-free) ----------------
__device__ float g_Y[9 * NMAX * 128];   // GEMM output, chunked [tile][node][128] (230 MB)
__device__ float g_h0[NMAX * FIN];
__device__ float g_h1[NMAX * FIN];
__device__ int   g_cnt[NB];
__device__ int   g_off[NB + 64];
__device__ int   g_cur[NB];
__device__ int   g_srcs[800000 + 64];
__device__ float g_inv[NB];
__device__ int   g_bsum[256];

// ---------------- PTX helpers (baseline sm_80-level, no 'a' features) ----------
__device__ __forceinline__ uint32_t smem_u32(const void* p) {
    uint32_t a;
    asm("{ .reg .u64 t; cvta.to.shared.u64 t, %1; cvt.u32.u64 %0, t; }" : "=r"(a) : "l"(p));
    return a;
}
__device__ __forceinline__ void ldsm4(uint32_t* r, uint32_t addr) {
    asm volatile("ldmatrix.sync.aligned.m8n8.x4.shared.b16 {%0,%1,%2,%3}, [%4];"
                 : "=r"(r[0]), "=r"(r[1]), "=r"(r[2]), "=r"(r[3]) : "r"(addr));
}
__device__ __forceinline__ void ldsm2(uint32_t* r, uint32_t addr) {
    asm volatile("ldmatrix.sync.aligned.m8n8.x2.shared.b16 {%0,%1}, [%2];"
                 : "=r"(r[0]), "=r"(r[1]) : "r"(addr));
}
__device__ __forceinline__ void mma16816(float* c, const uint32_t* a, const uint32_t* b) {
    asm volatile("mma.sync.aligned.m16n8k16.row.col.f32.bf16.bf16.f32 "
                 "{%0,%1,%2,%3}, {%4,%5,%6,%7}, {%8,%9}, {%0,%1,%2,%3};"
                 : "+f"(c[0]), "+f"(c[1]), "+f"(c[2]), "+f"(c[3])
                 : "r"(a[0]), "r"(a[1]), "r"(a[2]), "r"(a[3]), "r"(b[0]), "r"(b[1]));
}

// hi/lo bf16 split + pack pair into one u32 (low half = first element)
__device__ __forceinline__ void split_pack(float a, float b, uint32_t& hi, uint32_t& lo) {
    __nv_bfloat16 ah = __float2bfloat16(a), bh = __float2bfloat16(b);
    __nv_bfloat162 hh; hh.x = ah; hh.y = bh;
    hi = *reinterpret_cast<uint32_t*>(&hh);
    __nv_bfloat162 ll;
    ll.x = __float2bfloat16(a - __bfloat162float(ah));
    ll.y = __float2bfloat16(b - __bfloat162float(bh));
    lo = *reinterpret_cast<uint32_t*>(&ll);
}

// ---------------- CSR build ----------------
__global__ void zero_cnt_k() {
    int i = blockIdx.x * blockDim.x + threadIdx.x;
    if (i < NB) g_cnt[i] = 0;
}
__global__ void count_k(const int* __restrict__ dst, const int* __restrict__ et, int e) {
    int i = blockIdx.x * blockDim.x + threadIdx.x;
    if (i < e) atomicAdd(&g_cnt[dst[i] * RREL + et[i]], 1);
}

#define SCAN_T 256
#define SCAN_I 8
#define SCAN_E (SCAN_T * SCAN_I)                 // 2048
#define SCAN_NBLK ((NB + SCAN_E - 1) / SCAN_E)   // 196

__global__ void scan1_k() {
    __shared__ int sh[SCAN_T];
    int b = blockIdx.x, t = threadIdx.x;
    int base = b * SCAN_E + t * SCAN_I;
    int v[SCAN_I]; int s = 0;
#pragma unroll
    for (int i = 0; i < SCAN_I; i++) {
        int idx = base + i;
        v[i] = (idx < NB) ? g_cnt[idx] : 0;
        s += v[i];
    }
    sh[t] = s; __syncthreads();
    for (int off = 1; off < SCAN_T; off <<= 1) {
        int x = (t >= off) ? sh[t - off] : 0;
        __syncthreads();
        sh[t] += x;
        __syncthreads();
    }
    if (t == SCAN_T - 1) g_bsum[b] = sh[t];
    int excl = sh[t] - s;
#pragma unroll
    for (int i = 0; i < SCAN_I; i++) {
        int idx = base + i;
        if (idx < NB) g_off[idx] = excl;
        excl += v[i];
    }
}
__global__ void scan2_k() {
    __shared__ int sh[SCAN_T];
    int t = threadIdx.x;
    int v = (t < SCAN_NBLK) ? g_bsum[t] : 0;
    sh[t] = v; __syncthreads();
    for (int off = 1; off < SCAN_T; off <<= 1) {
        int x = (t >= off) ? sh[t - off] : 0;
        __syncthreads();
        sh[t] += x;
        __syncthreads();
    }
    if (t < SCAN_NBLK) g_bsum[t] = sh[t] - v;
}
__global__ void scan3_k(int e) {
    int i = blockIdx.x * blockDim.x + threadIdx.x;
    if (i < NB) {
        int o = g_off[i] + g_bsum[i / SCAN_E];
        g_off[i] = o;
        g_cur[i] = o;
        int c = g_cnt[i];
        g_inv[i] = 1.0f / (float)(c > 1 ? c : 1);
    }
    if (i == 0) g_off[NB] = e;
}
__global__ void fill_k(const int* __restrict__ src, const int* __restrict__ dst,
                       const int* __restrict__ et, int e) {
    int i = blockIdx.x * blockDim.x + threadIdx.x;
    if (i < e) {
        int bin = dst[i] * RREL + et[i];
        int slot = atomicAdd(&g_cur[bin], 1);
        g_srcs[slot] = src[i];
    }
}

// ---------------- HMMA GEMM: Y = X @ [root | W0..W7], hi/lo bf16 split --------
// SMEM layout: rows of 256B (128 bf16), 16 chunks of 16B, chunk index XOR-swizzled
// by (row & 7) for conflict-free ldmatrix.
// A: [128 rows (M)][128 cols (K)]   B: [NT rows (N)][128 cols (K)] == col-major B.
template<int FOUT>
__global__ void __launch_bounds__(256, 1) gemm_mma_k(const float* __restrict__ X,
                                                     const float* __restrict__ root,
                                                     const float* __restrict__ W,
                                                     float* __restrict__ Y, int n) {
    constexpr int NT    = (FOUT == 128) ? 128 : 144;
    constexpr int TILES = (FOUT == 128) ? 3 : 1;     // N-tiles per block (grid.y groups)
    constexpr int WN    = NT / 2;                     // warp N span (64 or 72)
    constexpr int NB8   = WN / 8;                     // n8 blocks per warp (8 or 9)
    constexpr int LD    = (FOUT == 128) ? 128 : 144;  // Y row stride
    constexpr int A_HI = 0, A_LO = 32768, B_HI = 65536, B_LO = 65536 + NT * 256;

    extern __shared__ char sm[];
    const uint32_t sb = smem_u32(sm);
    const int tid = threadIdx.x, lane = tid & 31, wid = tid >> 5;
    const int wm = wid & 3, wn = wid >> 2;
    const int m0 = blockIdx.x * 128;

    // ---- A conversion (once per block): 2048 chunks of 8 elems ----
    for (int i = tid; i < 128 * 16; i += 256) {
        int row = i >> 4, c = i & 15;
        int g = m0 + row;
        float v[8];
        if (g < n) {
            const float4* p = reinterpret_cast<const float4*>(X + (size_t)g * 128 + c * 8);
            float4 f0 = p[0], f1 = p[1];
            v[0]=f0.x; v[1]=f0.y; v[2]=f0.z; v[3]=f0.w; v[4]=f1.x; v[5]=f1.y; v[6]=f1.z; v[7]=f1.w;
        } else {
#pragma unroll
            for (int j = 0; j < 8; j++) v[j] = 0.f;
        }
        uint32_t hi[4], lo[4];
#pragma unroll
        for (int j = 0; j < 4; j++) split_pack(v[2*j], v[2*j+1], hi[j], lo[j]);
        uint32_t off = (uint32_t)row * 256 + ((uint32_t)(c ^ (row & 7)) << 4);
        *reinterpret_cast<uint4*>(sm + A_HI + off) = make_uint4(hi[0], hi[1], hi[2], hi[3]);
        *reinterpret_cast<uint4*>(sm + A_LO + off) = make_uint4(lo[0], lo[1], lo[2], lo[3]);
    }

    // lane-invariant ldmatrix addressing
    const int sub  = lane >> 3;
    const int rowa = wm * 32 + (sub & 1) * 8 + (lane & 7);
    const int csel = sub >> 1;
    const int rs   = lane & 7;
    const int lb   = lane & 15;
    const int subb = lb >> 3;
    const int rsb  = lb & 7;

    for (int it = 0; it < TILES; it++) {
        const int t = blockIdx.y * TILES + it;

        // ---- B conversion (per tile): Bs[ln][k] = Wcat[k][tile_n0 + ln] ----
        __syncthreads();  // protect previous tile's B reads
        for (int i = tid; i < 16 * NT; i += 256) {
            int c = i / NT, ln = i % NT;
            float v[8];
#pragma unroll
            for (int kk = 0; kk < 8; kk++) {
                int k = c * 8 + kk;
                if (FOUT == 128)
                    v[kk] = (t == 0) ? root[k * 128 + ln]
                                     : W[((size_t)(t - 1) * 128 + k) * 128 + ln];
                else
                    v[kk] = (ln < 16) ? root[k * 16 + ln]
                                      : W[((size_t)((ln - 16) >> 4) * 128 + k) * 16 + ((ln - 16) & 15)];
            }
            uint32_t hi[4], lo[4];
#pragma unroll
            for (int j = 0; j < 4; j++) split_pack(v[2*j], v[2*j+1], hi[j], lo[j]);
            uint32_t off = (uint32_t)ln * 256 + ((uint32_t)(c ^ (ln & 7)) << 4);
            *reinterpret_cast<uint4*>(sm + B_HI + off) = make_uint4(hi[0], hi[1], hi[2], hi[3]);
            *reinterpret_cast<uint4*>(sm + B_LO + off) = make_uint4(lo[0], lo[1], lo[2], lo[3]);
        }
        __syncthreads();

        // ---- compute: 3-product hi/lo accumulate ----
        float acc[2][NB8][4];
#pragma unroll
        for (int mt = 0; mt < 2; mt++)
#pragma unroll
            for (int nb = 0; nb < NB8; nb++)
#pragma unroll
                for (int j = 0; j < 4; j++) acc[mt][nb][j] = 0.f;

#pragma unroll
        for (int ks = 0; ks < 8; ks++) {
            uint32_t ca = (uint32_t)((2 * ks + csel) ^ rs) << 4;
            uint32_t ah0[4], ah1[4], al0[4], al1[4];
            ldsm4(ah0, sb + A_HI + (uint32_t)rowa * 256 + ca);
            ldsm4(ah1, sb + A_HI + (uint32_t)(rowa + 16) * 256 + ca);
            ldsm4(al0, sb + A_LO + (uint32_t)rowa * 256 + ca);
            ldsm4(al1, sb + A_LO + (uint32_t)(rowa + 16) * 256 + ca);
            uint32_t cb = (uint32_t)((2 * ks + subb) ^ rsb) << 4;
#pragma unroll
            for (int nb = 0; nb < NB8; nb++) {
                uint32_t rowb = (uint32_t)(wn * WN + nb * 8 + rsb);
                uint32_t bh[2], bl[2];
                ldsm2(bh, sb + B_HI + rowb * 256 + cb);
                ldsm2(bl, sb + B_LO + rowb * 256 + cb);
                mma16816(acc[0][nb], ah0, bh);
                mma16816(acc[1][nb], ah1, bh);
                mma16816(acc[0][nb], ah0, bl);
                mma16816(acc[1][nb], ah1, bl);
                mma16816(acc[0][nb], al0, bh);
                mma16816(acc[1][nb], al1, bh);
            }
        }

        // ---- epilogue ----
#pragma unroll
        for (int mt = 0; mt < 2; mt++) {
            int row = m0 + wm * 32 + mt * 16 + (lane >> 2);
#pragma unroll
            for (int nb = 0; nb < NB8; nb++) {
                int col = wn * WN + nb * 8 + (lane & 3) * 2;
                float* d0;
                if (FOUT == 128) d0 = Y + (size_t)t * CS + (size_t)row * LD + col;
                else             d0 = Y + (size_t)row * LD + col;
                if (row < n)
                    *reinterpret_cast<float2*>(d0) = make_float2(acc[mt][nb][0], acc[mt][nb][1]);
                if (row + 8 < n)
                    *reinterpret_cast<float2*>(d0 + (size_t)8 * LD) =
                        make_float2(acc[mt][nb][2], acc[mt][nb][3]);
            }
        }
    }
}

// ---------------- aggregation (CSR gather over pre-multiplied Y) ----------------
__device__ __forceinline__ void fma4(float4& a, float w, const float4 v) {
    a.x = fmaf(w, v.x, a.x); a.y = fmaf(w, v.y, a.y);
    a.z = fmaf(w, v.z, a.z); a.w = fmaf(w, v.w, a.w);
}

// H=128 layers: one warp per node, lane covers 4 features
__global__ void agg_h_k(const float* __restrict__ bias, float* __restrict__ out,
                        int n, int relu) {
    int w = (blockIdx.x * blockDim.x + threadIdx.x) >> 5;
    int lane = threadIdx.x & 31;
    if (w >= n) return;
    const float* Y = g_Y;
    float4 acc = *reinterpret_cast<const float4*>(Y + (size_t)w * 128 + lane * 4);
    float4 bb = *reinterpret_cast<const float4*>(bias + lane * 4);
    acc.x += bb.x; acc.y += bb.y; acc.z += bb.z; acc.w += bb.w;
#pragma unroll
    for (int r = 0; r < RREL; r++) {
        int b = w * RREL + r;
        int s0 = g_off[b], s1 = g_off[b + 1];
        float wt = g_inv[b];
        const float* base = Y + (size_t)(r + 1) * CS;
        for (int s = s0; s < s1; s++) {
            int j = g_srcs[s];
            float4 v = *reinterpret_cast<const float4*>(base + (size_t)j * 128 + lane * 4);
            fma4(acc, wt, v);
        }
    }
    if (relu) {
        acc.x = fmaxf(acc.x, 0.f); acc.y = fmaxf(acc.y, 0.f);
        acc.z = fmaxf(acc.z, 0.f); acc.w = fmaxf(acc.w, 0.f);
    }
    *reinterpret_cast<float4*>(out + (size_t)w * 128 + lane * 4) = acc;
}

// H=16 output layer: 4 threads per node (float4 each), Y row-major stride 144
__global__ void agg_o_k(const float* __restrict__ bias, float* __restrict__ out, int n) {
    int gt = blockIdx.x * blockDim.x + threadIdx.x;
    int node = gt >> 2, sub = gt & 3;
    if (node >= n) return;
    const float* Y = g_Y;
    float4 acc = *reinterpret_cast<const float4*>(Y + (size_t)node * 144 + sub * 4);
    float4 bb = *reinterpret_cast<const float4*>(bias + sub * 4);
    acc.x += bb.x; acc.y += bb.y; acc.z += bb.z; acc.w += bb.w;
#pragma unroll
    for (int r = 0; r < RREL; r++) {
        int b = node * RREL + r;
        int s0 = g_off[b], s1 = g_off[b + 1];
        float wt = g_inv[b];
        int col = 16 + r * 16 + sub * 4;
        for (int s = s0; s < s1; s++) {
            int j = g_srcs[s];
            float4 v = *reinterpret_cast<const float4*>(Y + (size_t)j * 144 + col);
            fma4(acc, wt, v);
        }
    }
    *reinterpret_cast<float4*>(out + (size_t)node * 16 + sub * 4) = acc;
}

// ---------------- host ----------------
extern "C" void kernel_launch(void* const* d_in, const int* in_sizes, int n_in,
                              void* d_out, int out_size) {
    const float* x  = (const float*)d_in[0];
    const int* eidx = (const int*)d_in[1];
    const int* et   = (const int*)d_in[2];
    const float* w0 = (const float*)d_in[3];
    const float* r0 = (const float*)d_in[4];
    const float* b0 = (const float*)d_in[5];
    const float* w1 = (const float*)d_in[6];
    const float* r1 = (const float*)d_in[7];
    const float* b1 = (const float*)d_in[8];
    const float* w2 = (const float*)d_in[9];
    const float* r2 = (const float*)d_in[10];
    const float* b2 = (const float*)d_in[11];
    float* out = (float*)d_out;

    int n = in_sizes[0] / FIN;   // 50000
    int e = in_sizes[2];         // 800000
    const int* src = eidx;
    const int* dst = eidx + e;

    float *Y, *h0, *h1;
    cudaGetSymbolAddress((void**)&Y, g_Y);
    cudaGetSymbolAddress((void**)&h0, g_h0);
    cudaGetSymbolAddress((void**)&h1, g_h1);

    const int SMEM128 = 65536 + 2 * 128 * 256;   // 131072
    const int SMEM144 = 65536 + 2 * 144 * 256;   // 139264
    cudaFuncSetAttribute(gemm_mma_k<128>, cudaFuncAttributeMaxDynamicSharedMemorySize, SMEM128);
    cudaFuncSetAttribute(gemm_mma_k<16>,  cudaFuncAttributeMaxDynamicSharedMemorySize, SMEM144);

    // CSR build (edge structure shared by all 3 layers)
    zero_cnt_k<<<(NB + 255) / 256, 256>>>();
    count_k<<<(e + 255) / 256, 256>>>(dst, et, e);
    scan1_k<<<SCAN_NBLK, SCAN_T>>>();
    scan2_k<<<1, SCAN_T>>>();
    scan3_k<<<(NB + 255) / 256, 256>>>(e);
    fill_k<<<(e + 255) / 256, 256>>>(src, dst, et, e);

    int mblocks = (n + 127) / 128;   // 391
    // Layer 0
    gemm_mma_k<128><<<dim3(mblocks, 3), 256, SMEM128>>>(x, r0, w0, Y, n);
    agg_h_k<<<(n * 32 + 255) / 256, 256>>>(b0, h0, n, 1);
    // Layer 1
    gemm_mma_k<128><<<dim3(mblocks, 3), 256, SMEM128>>>(h0, r1, w1, Y, n);
    agg_h_k<<<(n * 32 + 255) / 256, 256>>>(b1, h1, n, 1);
    // Layer 2
    gemm_mma_k<16><<<dim3(mblocks, 1), 256, SMEM144>>>(h1, r2, w2, Y, n);
    agg_o_k<<<(n * 4 + 255) / 256, 256>>>(b2, out, n);
}

// round 8
// speedup vs baseline: 5.5250x; 1.3205x over previous
#include <cuda_runtime.h>
#include <cuda_bf16.h>
#include <cstdint>

// Problem constants (fixed dataset)
#define NMAX 50000
#define RREL 8
#define FIN  128
#define NB   (NMAX * RREL)          // 400000 segment bins
#define CS   ((size_t)NMAX * 128)   // Y chunk stride (floats)
#define EMAX 800000

// ---------------- device scratch (allocation-free) ----------------
__device__ float g_Y[9 * NMAX * 128];   // GEMM output, chunked [tile][node][128] (230 MB)
__device__ float g_h0[NMAX * FIN];
__device__ float g_h1[NMAX * FIN];
__device__ int   g_cnt[NB];
__device__ int   g_off[NB + 64];
__device__ int   g_cur[NB];
__device__ int   g_srcs[EMAX + 64];     // packed: src | (rel << 20)
__device__ float g_wt[EMAX + 64];       // per-edge 1/deg weight
__device__ float g_inv[NB];
__device__ int   g_bsum[256];
// Pre-split, pre-swizzled B images (hi/lo), max(9*128,144)*256 bytes each
__device__ unsigned char g_Bhi[294912];
__device__ unsigned char g_Blo[294912];

// ---------------- PTX helpers (baseline sm_80-level, no 'a' features) ----------
__device__ __forceinline__ uint32_t smem_u32(const void* p) {
    uint32_t a;
    asm("{ .reg .u64 t; cvta.to.shared.u64 t, %1; cvt.u32.u64 %0, t; }" : "=r"(a) : "l"(p));
    return a;
}
__device__ __forceinline__ void ldsm4(uint32_t* r, uint32_t addr) {
    asm volatile("ldmatrix.sync.aligned.m8n8.x4.shared.b16 {%0,%1,%2,%3}, [%4];"
                 : "=r"(r[0]), "=r"(r[1]), "=r"(r[2]), "=r"(r[3]) : "r"(addr));
}
__device__ __forceinline__ void ldsm2(uint32_t* r, uint32_t addr) {
    asm volatile("ldmatrix.sync.aligned.m8n8.x2.shared.b16 {%0,%1}, [%2];"
                 : "=r"(r[0]), "=r"(r[1]) : "r"(addr));
}
__device__ __forceinline__ void mma16816(float* c, const uint32_t* a, const uint32_t* b) {
    asm volatile("mma.sync.aligned.m16n8k16.row.col.f32.bf16.bf16.f32 "
                 "{%0,%1,%2,%3}, {%4,%5,%6,%7}, {%8,%9}, {%0,%1,%2,%3};"
                 : "+f"(c[0]), "+f"(c[1]), "+f"(c[2]), "+f"(c[3])
                 : "r"(a[0]), "r"(a[1]), "r"(a[2]), "r"(a[3]), "r"(b[0]), "r"(b[1]));
}
__device__ __forceinline__ void cpa16(uint32_t smem, const void* g) {
    asm volatile("cp.async.cg.shared.global [%0], [%1], 16;" :: "r"(smem), "l"(g));
}
#define CP_COMMIT() asm volatile("cp.async.commit_group;" ::: "memory")
#define CP_WAIT0()  asm volatile("cp.async.wait_group 0;" ::: "memory")

// hi/lo bf16 split + pack pair into one u32 (low half = first element)
__device__ __forceinline__ void split_pack(float a, float b, uint32_t& hi, uint32_t& lo) {
    __nv_bfloat16 ah = __float2bfloat16(a), bh = __float2bfloat16(b);
    __nv_bfloat162 hh; hh.x = ah; hh.y = bh;
    hi = *reinterpret_cast<uint32_t*>(&hh);
    __nv_bfloat162 ll;
    ll.x = __float2bfloat16(a - __bfloat162float(ah));
    ll.y = __float2bfloat16(b - __bfloat162float(bh));
    lo = *reinterpret_cast<uint32_t*>(&ll);
}

// ---------------- CSR build ----------------
__global__ void zero_cnt_k() {
    int i = blockIdx.x * blockDim.x + threadIdx.x;
    if (i < NB) g_cnt[i] = 0;
}
__global__ void count_k(const int* __restrict__ dst, const int* __restrict__ et, int e) {
    int i = blockIdx.x * blockDim.x + threadIdx.x;
    if (i < e) atomicAdd(&g_cnt[dst[i] * RREL + et[i]], 1);
}

#define SCAN_T 256
#define SCAN_I 8
#define SCAN_E (SCAN_T * SCAN_I)                 // 2048
#define SCAN_NBLK ((NB + SCAN_E - 1) / SCAN_E)   // 196

__global__ void scan1_k() {
    __shared__ int sh[SCAN_T];
    int b = blockIdx.x, t = threadIdx.x;
    int base = b * SCAN_E + t * SCAN_I;
    int v[SCAN_I]; int s = 0;
#pragma unroll
    for (int i = 0; i < SCAN_I; i++) {
        int idx = base + i;
        v[i] = (idx < NB) ? g_cnt[idx] : 0;
        s += v[i];
    }
    sh[t] = s; __syncthreads();
    for (int off = 1; off < SCAN_T; off <<= 1) {
        int x = (t >= off) ? sh[t - off] : 0;
        __syncthreads();
        sh[t] += x;
        __syncthreads();
    }
    if (t == SCAN_T - 1) g_bsum[b] = sh[t];
    int excl = sh[t] - s;
#pragma unroll
    for (int i = 0; i < SCAN_I; i++) {
        int idx = base + i;
        if (idx < NB) g_off[idx] = excl;
        excl += v[i];
    }
}
__global__ void scan2_k() {
    __shared__ int sh[SCAN_T];
    int t = threadIdx.x;
    int v = (t < SCAN_NBLK) ? g_bsum[t] : 0;
    sh[t] = v; __syncthreads();
    for (int off = 1; off < SCAN_T; off <<= 1) {
        int x = (t >= off) ? sh[t - off] : 0;
        __syncthreads();
        sh[t] += x;
        __syncthreads();
    }
    if (t < SCAN_NBLK) g_bsum[t] = sh[t] - v;
}
__global__ void scan3_k(int e) {
    int i = blockIdx.x * blockDim.x + threadIdx.x;
    if (i < NB) {
        int o = g_off[i] + g_bsum[i / SCAN_E];
        g_off[i] = o;
        g_cur[i] = o;
        int c = g_cnt[i];
        g_inv[i] = 1.0f / (float)(c > 1 ? c : 1);
    }
    if (i == 0) g_off[NB] = e;
}
__global__ void fill_k(const int* __restrict__ src, const int* __restrict__ dst,
                       const int* __restrict__ et, int e) {
    int i = blockIdx.x * blockDim.x + threadIdx.x;
    if (i < e) {
        int t = et[i];
        int bin = dst[i] * RREL + t;
        int slot = atomicAdd(&g_cur[bin], 1);
        g_srcs[slot] = src[i] | (t << 20);
        g_wt[slot] = g_inv[bin];
    }
}

// ---------------- B precompute: split + swizzle weight images into global ------
// Image per tile t: NT rows x 256B (128 bf16), chunk XOR-swizzled by (row & 7).
template<int FOUT>
__global__ void conv_b_k(const float* __restrict__ root, const float* __restrict__ W) {
    constexpr int NT  = (FOUT == 128) ? 128 : 144;
    constexpr int TOT = (FOUT == 128) ? 9 : 1;
    int i = blockIdx.x * blockDim.x + threadIdx.x;
    if (i >= TOT * 16 * NT) return;
    int t = i / (16 * NT);
    int j = i % (16 * NT);
    int c = j / NT, ln = j % NT;
    float v[8];
#pragma unroll
    for (int kk = 0; kk < 8; kk++) {
        int k = c * 8 + kk;
        if (FOUT == 128)
            v[kk] = (t == 0) ? root[k * 128 + ln]
                             : W[((size_t)(t - 1) * 128 + k) * 128 + ln];
        else
            v[kk] = (ln < 16) ? root[k * 16 + ln]
                              : W[((size_t)((ln - 16) >> 4) * 128 + k) * 16 + ((ln - 16) & 15)];
    }
    uint32_t hi[4], lo[4];
#pragma unroll
    for (int q = 0; q < 4; q++) split_pack(v[2*q], v[2*q+1], hi[q], lo[q]);
    uint32_t off = (uint32_t)t * (NT * 256) + (uint32_t)ln * 256 + ((uint32_t)(c ^ (ln & 7)) << 4);
    *reinterpret_cast<uint4*>(g_Bhi + off) = make_uint4(hi[0], hi[1], hi[2], hi[3]);
    *reinterpret_cast<uint4*>(g_Blo + off) = make_uint4(lo[0], lo[1], lo[2], lo[3]);
}

// ---------------- HMMA GEMM: Y = X @ [root | W0..W7], hi/lo bf16 split --------
// A: converted in-kernel into swizzled smem. B: cp.async from precomputed images,
// double-buffered across the TILES N-tiles.
template<int FOUT>
__global__ void __launch_bounds__(256, 1) gemm_mma_k(const float* __restrict__ X,
                                                     float* __restrict__ Y, int n) {
    constexpr int NT    = (FOUT == 128) ? 128 : 144;
    constexpr int TILES = (FOUT == 128) ? 3 : 1;     // N-tiles per block (grid.y groups)
    constexpr int WN    = NT / 2;                     // warp N span (64 or 72)
    constexpr int NB8   = WN / 8;                     // n8 blocks per warp (8 or 9)
    constexpr int LD    = (FOUT == 128) ? 128 : 144;  // Y row stride
    constexpr int TB    = NT * 256;                   // tile image bytes (hi or lo)
    constexpr int A_HI = 0, A_LO = 32768, B_BASE = 65536, BSTEP = 2 * TB;

    extern __shared__ char sm[];
    const uint32_t sb = smem_u32(sm);
    const int tid = threadIdx.x, lane = tid & 31, wid = tid >> 5;
    const int wm = wid & 3, wn = wid >> 2;
    const int m0 = blockIdx.x * 128;
    const int t0 = blockIdx.y * TILES;

    // ---- kick off B copy for first tile into buf 0 ----
    {
        uint32_t b0 = sb + B_BASE;
        const unsigned char* shi = g_Bhi + (size_t)t0 * TB;
        const unsigned char* slo = g_Blo + (size_t)t0 * TB;
        for (int i = tid; i < NT * 16; i += 256) {
            cpa16(b0 + i * 16, shi + i * 16);
            cpa16(b0 + TB + i * 16, slo + i * 16);
        }
        CP_COMMIT();
    }

    // ---- A conversion (overlaps B copy): 2048 chunks of 8 elems ----
    for (int i = tid; i < 128 * 16; i += 256) {
        int row = i >> 4, c = i & 15;
        int g = m0 + row;
        float v[8];
        if (g < n) {
            const float4* p = reinterpret_cast<const float4*>(X + (size_t)g * 128 + c * 8);
            float4 f0 = p[0], f1 = p[1];
            v[0]=f0.x; v[1]=f0.y; v[2]=f0.z; v[3]=f0.w; v[4]=f1.x; v[5]=f1.y; v[6]=f1.z; v[7]=f1.w;
        } else {
#pragma unroll
            for (int j = 0; j < 8; j++) v[j] = 0.f;
        }
        uint32_t hi[4], lo[4];
#pragma unroll
        for (int j = 0; j < 4; j++) split_pack(v[2*j], v[2*j+1], hi[j], lo[j]);
        uint32_t off = (uint32_t)row * 256 + ((uint32_t)(c ^ (row & 7)) << 4);
        *reinterpret_cast<uint4*>(sm + A_HI + off) = make_uint4(hi[0], hi[1], hi[2], hi[3]);
        *reinterpret_cast<uint4*>(sm + A_LO + off) = make_uint4(lo[0], lo[1], lo[2], lo[3]);
    }

    // lane-invariant ldmatrix addressing
    const int sub  = lane >> 3;
    const int rowa = wm * 32 + (sub & 1) * 8 + (lane & 7);
    const int csel = sub >> 1;
    const int rs   = lane & 7;
    const int lb   = lane & 15;
    const int subb = lb >> 3;
    const int rsb  = lb & 7;

    int buf = 0;
    for (int it = 0; it < TILES; it++) {
        const int t = t0 + it;
        CP_WAIT0();
        __syncthreads();   // B(it) resident; all threads done with buf^1's previous compute

        // prefetch next tile's B into the other buffer
        if (it + 1 < TILES) {
            uint32_t bn = sb + B_BASE + (buf ^ 1) * BSTEP;
            const unsigned char* shi = g_Bhi + (size_t)(t + 1) * TB;
            const unsigned char* slo = g_Blo + (size_t)(t + 1) * TB;
            for (int i = tid; i < NT * 16; i += 256) {
                cpa16(bn + i * 16, shi + i * 16);
                cpa16(bn + TB + i * 16, slo + i * 16);
            }
            CP_COMMIT();
        }

        const uint32_t bh_base = sb + B_BASE + buf * BSTEP;
        const uint32_t bl_base = bh_base + TB;

        // ---- compute: 3-product hi/lo accumulate ----
        float acc[2][NB8][4];
#pragma unroll
        for (int mt = 0; mt < 2; mt++)
#pragma unroll
            for (int nb = 0; nb < NB8; nb++)
#pragma unroll
                for (int j = 0; j < 4; j++) acc[mt][nb][j] = 0.f;

#pragma unroll
        for (int ks = 0; ks < 8; ks++) {
            uint32_t ca = (uint32_t)((2 * ks + csel) ^ rs) << 4;
            uint32_t ah0[4], ah1[4], al0[4], al1[4];
            ldsm4(ah0, sb + A_HI + (uint32_t)rowa * 256 + ca);
            ldsm4(ah1, sb + A_HI + (uint32_t)(rowa + 16) * 256 + ca);
            ldsm4(al0, sb + A_LO + (uint32_t)rowa * 256 + ca);
            ldsm4(al1, sb + A_LO + (uint32_t)(rowa + 16) * 256 + ca);
            uint32_t cb = (uint32_t)((2 * ks + subb) ^ rsb) << 4;
#pragma unroll
            for (int nb = 0; nb < NB8; nb++) {
                uint32_t rowb = (uint32_t)(wn * WN + nb * 8 + rsb);
                uint32_t bh[2], bl[2];
                ldsm2(bh, bh_base + rowb * 256 + cb);
                ldsm2(bl, bl_base + rowb * 256 + cb);
                mma16816(acc[0][nb], ah0, bh);
                mma16816(acc[1][nb], ah1, bh);
                mma16816(acc[0][nb], ah0, bl);
                mma16816(acc[1][nb], ah1, bl);
                mma16816(acc[0][nb], al0, bh);
                mma16816(acc[1][nb], al1, bh);
            }
        }

        // ---- epilogue (registers -> global, no smem) ----
#pragma unroll
        for (int mt = 0; mt < 2; mt++) {
            int row = m0 + wm * 32 + mt * 16 + (lane >> 2);
#pragma unroll
            for (int nb = 0; nb < NB8; nb++) {
                int col = wn * WN + nb * 8 + (lane & 3) * 2;
                float* d0;
                if (FOUT == 128) d0 = Y + (size_t)t * CS + (size_t)row * LD + col;
                else             d0 = Y + (size_t)row * LD + col;
                if (row < n)
                    *reinterpret_cast<float2*>(d0) = make_float2(acc[mt][nb][0], acc[mt][nb][1]);
                if (row + 8 < n)
                    *reinterpret_cast<float2*>(d0 + (size_t)8 * LD) =
                        make_float2(acc[mt][nb][2], acc[mt][nb][3]);
            }
        }
        buf ^= 1;
    }
}

// ---------------- aggregation (flattened CSR gather over pre-multiplied Y) -----
__device__ __forceinline__ void fma4(float4& a, float w, const float4 v) {
    a.x = fmaf(w, v.x, a.x); a.y = fmaf(w, v.y, a.y);
    a.z = fmaf(w, v.z, a.z); a.w = fmaf(w, v.w, a.w);
}
__device__ __forceinline__ const float4* yrow(const float* Y, int packed, int lane4) {
    int src = packed & 0xFFFFF, rel = packed >> 20;
    return reinterpret_cast<const float4*>(Y + (size_t)(rel + 1) * CS + (size_t)src * 128 + lane4);
}

// H=128 layers: one warp per node, lane covers 4 features; single flat edge loop
__global__ void agg_h_k(const float* __restrict__ bias, float* __restrict__ out,
                        int n, int relu) {
    int w = (blockIdx.x * blockDim.x + threadIdx.x) >> 5;
    int lane4 = (threadIdx.x & 31) * 4;
    if (w >= n) return;
    const float* Y = g_Y;
    float4 acc = *reinterpret_cast<const float4*>(Y + (size_t)w * 128 + lane4);
    float4 bb = *reinterpret_cast<const float4*>(bias + lane4);
    acc.x += bb.x; acc.y += bb.y; acc.z += bb.z; acc.w += bb.w;

    int s = g_off[w * RREL];
    const int s1 = g_off[w * RREL + RREL];
    for (; s + 4 <= s1; s += 4) {
        int p0 = g_srcs[s], p1 = g_srcs[s+1], p2 = g_srcs[s+2], p3 = g_srcs[s+3];
        float w0 = g_wt[s], w1 = g_wt[s+1], w2 = g_wt[s+2], w3 = g_wt[s+3];
        float4 v0 = *yrow(Y, p0, lane4);
        float4 v1 = *yrow(Y, p1, lane4);
        float4 v2 = *yrow(Y, p2, lane4);
        float4 v3 = *yrow(Y, p3, lane4);
        fma4(acc, w0, v0); fma4(acc, w1, v1); fma4(acc, w2, v2); fma4(acc, w3, v3);
    }
    for (; s < s1; s++) {
        int p = g_srcs[s]; float wt = g_wt[s];
        float4 v = *yrow(Y, p, lane4);
        fma4(acc, wt, v);
    }
    if (relu) {
        acc.x = fmaxf(acc.x, 0.f); acc.y = fmaxf(acc.y, 0.f);
        acc.z = fmaxf(acc.z, 0.f); acc.w = fmaxf(acc.w, 0.f);
    }
    *reinterpret_cast<float4*>(out + (size_t)w * 128 + lane4) = acc;
}

// H=16 output layer: 4 threads per node (float4 each), Y row-major stride 144
__global__ void agg_o_k(const float* __restrict__ bias, float* __restrict__ out, int n) {
    int gt = blockIdx.x * blockDim.x + threadIdx.x;
    int node = gt >> 2, sub4 = (gt & 3) * 4;
    if (node >= n) return;
    const float* Y = g_Y;
    float4 acc = *reinterpret_cast<const float4*>(Y + (size_t)node * 144 + sub4);
    float4 bb = *reinterpret_cast<const float4*>(bias + sub4);
    acc.x += bb.x; acc.y += bb.y; acc.z += bb.z; acc.w += bb.w;

    int s = g_off[node * RREL];
    const int s1 = g_off[node * RREL + RREL];
    for (; s + 2 <= s1; s += 2) {
        int p0 = g_srcs[s], p1 = g_srcs[s+1];
        float w0 = g_wt[s], w1 = g_wt[s+1];
        const float4 v0 = *reinterpret_cast<const float4*>(
            Y + (size_t)(p0 & 0xFFFFF) * 144 + 16 + (p0 >> 20) * 16 + sub4);
        const float4 v1 = *reinterpret_cast<const float4*>(
            Y + (size_t)(p1 & 0xFFFFF) * 144 + 16 + (p1 >> 20) * 16 + sub4);
        fma4(acc, w0, v0); fma4(acc, w1, v1);
    }
    for (; s < s1; s++) {
        int p = g_srcs[s]; float wt = g_wt[s];
        const float4 v = *reinterpret_cast<const float4*>(
            Y + (size_t)(p & 0xFFFFF) * 144 + 16 + (p >> 20) * 16 + sub4);
        fma4(acc, wt, v);
    }
    *reinterpret_cast<float4*>(out + (size_t)node * 16 + sub4) = acc;
}

// ---------------- host ----------------
extern "C" void kernel_launch(void* const* d_in, const int* in_sizes, int n_in,
                              void* d_out, int out_size) {
    const float* x  = (const float*)d_in[0];
    const int* eidx = (const int*)d_in[1];
    const int* et   = (const int*)d_in[2];
    const float* w0 = (const float*)d_in[3];
    const float* r0 = (const float*)d_in[4];
    const float* b0 = (const float*)d_in[5];
    const float* w1 = (const float*)d_in[6];
    const float* r1 = (const float*)d_in[7];
    const float* b1 = (const float*)d_in[8];
    const float* w2 = (const float*)d_in[9];
    const float* r2 = (const float*)d_in[10];
    const float* b2 = (const float*)d_in[11];
    float* out = (float*)d_out;

    int n = in_sizes[0] / FIN;   // 50000
    int e = in_sizes[2];         // 800000
    const int* src = eidx;
    const int* dst = eidx + e;

    float *Y, *h0, *h1;
    cudaGetSymbolAddress((void**)&Y, g_Y);
    cudaGetSymbolAddress((void**)&h0, g_h0);
    cudaGetSymbolAddress((void**)&h1, g_h1);

    const int SMEM128 = 65536 + 2 * (2 * 128 * 256);   // A + 2 B buffers = 196608
    const int SMEM144 = 65536 + (2 * 144 * 256);       // A + 1 B buffer  = 139264
    cudaFuncSetAttribute(gemm_mma_k<128>, cudaFuncAttributeMaxDynamicSharedMemorySize, SMEM128);
    cudaFuncSetAttribute(gemm_mma_k<16>,  cudaFuncAttributeMaxDynamicSharedMemorySize, SMEM144);

    // CSR build (edge structure shared by all 3 layers)
    zero_cnt_k<<<(NB + 255) / 256, 256>>>();
    count_k<<<(e + 255) / 256, 256>>>(dst, et, e);
    scan1_k<<<SCAN_NBLK, SCAN_T>>>();
    scan2_k<<<1, SCAN_T>>>();
    scan3_k<<<(NB + 255) / 256, 256>>>(e);
    fill_k<<<(e + 255) / 256, 256>>>(src, dst, et, e);

    int mblocks = (n + 127) / 128;   // 391
    const int CB128 = (9 * 16 * 128 + 255) / 256;
    const int CB16  = (1 * 16 * 144 + 255) / 256;

    // Layer 0
    conv_b_k<128><<<CB128, 256>>>(r0, w0);
    gemm_mma_k<128><<<dim3(mblocks, 3), 256, SMEM128>>>(x, Y, n);
    agg_h_k<<<(n * 32 + 255) / 256, 256>>>(b0, h0, n, 1);
    // Layer 1
    conv_b_k<128><<<CB128, 256>>>(r1, w1);
    gemm_mma_k<128><<<dim3(mblocks, 3), 256, SMEM128>>>(h0, Y, n);
    agg_h_k<<<(n * 32 + 255) / 256, 256>>>(b1, h1, n, 1);
    // Layer 2
    conv_b_k<16><<<CB16, 256>>>(r2, w2);
    gemm_mma_k<16><<<dim3(mblocks, 1), 256, SMEM144>>>(h1, Y, n);
    agg_o_k<<<(n * 4 + 255) / 256, 256>>>(b2, out, n);
}